// round 7
// baseline (speedup 1.0000x reference)
#include <cuda_runtime.h>

#define NROWS 32768
#define DIM   128
#define NC    512
#define TOPK  10
#define MTILE 32
#define KT    32
#define CTILE 256                      // centers per GEMM block
#define CAND_STRIDE 81                 // padded candidate row stride (u64 keys)

__device__ float g_c2[NC];
__device__ float g_scores[(size_t)NROWS * NC];   // 64 MB scratch

// XLA GPU row-reduction for sum(v*v), 128-wide f32 row:
// single pass, 16-byte vectorized: lane t owns contiguous quad v[4t..4t+3],
// left-fold into scalar partial, then shfl_down tree offsets 16,8,4,2,1.
// (empirically bit-exact vs the reference — DO NOT CHANGE)
__device__ __forceinline__ float xla_row_sumsq(const float* __restrict__ row, int lane) {
    float4 v = *reinterpret_cast<const float4*>(row + 4 * lane);
    float p = __fmul_rn(v.x, v.x);
    p = __fadd_rn(p, __fmul_rn(v.y, v.y));
    p = __fadd_rn(p, __fmul_rn(v.z, v.z));
    p = __fadd_rn(p, __fmul_rn(v.w, v.w));
#pragma unroll
    for (int off = 16; off > 0; off >>= 1)
        p = __fadd_rn(p, __shfl_down_sync(0xffffffffu, p, off));
    return __shfl_sync(0xffffffffu, p, 0);
}

__global__ void c2_kernel(const float* __restrict__ cc) {
    int warp = threadIdx.x >> 5;
    int lane = threadIdx.x & 31;
    int c = blockIdx.x * 8 + warp;
    float s = xla_row_sumsq(cc + (size_t)c * DIM, lane);
    if (lane == 0) g_c2[c] = s;
}

__device__ __forceinline__ unsigned long long fma2(unsigned long long a,
                                                   unsigned long long b,
                                                   unsigned long long c) {
    unsigned long long d;
    asm("fma.rn.f32x2 %0, %1, %2, %3;" : "=l"(d) : "l"(a), "l"(b), "l"(c));
    return d;
}
__device__ __forceinline__ void unpack2(unsigned long long v, float& lo, float& hi) {
    asm("mov.b64 {%0, %1}, %2;" : "=f"(lo), "=f"(hi) : "l"(v));
}

// ============================ Kernel A: GEMM + distance ============================
// Block: 256 threads, 32 rows x 256 centers. Thread: 8 rows x 4 centers.
// smem: cs[KT][CTILE] 32KB + xs2[KT][MTILE] 8KB + x2s = ~40.2KB -> 3+ CTAs/SM.
#define GA_SMEM (KT * CTILE * 4 + KT * MTILE * 8 + MTILE * 4)

__global__ __launch_bounds__(256, 3)
void gemm_kernel(const float* __restrict__ x, const float* __restrict__ cc) {
    extern __shared__ char smraw[];
    float*  cs  = reinterpret_cast<float*>(smraw);                       // [KT][CTILE]
    float2* xs2 = reinterpret_cast<float2*>(smraw + KT * CTILE * 4);     // [KT][MTILE]
    float*  x2s = reinterpret_cast<float*>(smraw + KT * CTILE * 4 + KT * MTILE * 8);

    const int tx   = threadIdx.x;
    const int b    = blockIdx.x;
    const int cblk = b & 1;
    const int row0 = (b >> 1) * MTILE;
    const int lane = tx & 31;
    const int warp = tx >> 5;
    const int rg   = warp >> 1;              // 0..3
    const int cg   = warp & 1;               // 0..1
    const int rbase = rg * 8;
    const int cloc  = cg * 128 + lane * 4;   // local center base (0..252)
    const int cglob = cblk * CTILE + cloc;   // global center base

    // x2[row] exact XLA order; warp w does rows w, w+8, w+16, w+24
#pragma unroll
    for (int j = 0; j < 4; ++j) {
        int rl = warp + 8 * j;
        float s = xla_row_sumsq(x + (size_t)(row0 + rl) * DIM, lane);
        if (lane == 0) x2s[rl] = s;
    }

    unsigned long long acc[8][2];
#pragma unroll
    for (int r = 0; r < 8; ++r) { acc[r][0] = 0ull; acc[r][1] = 0ull; }

    const int cq = cloc >> 2;   // ulonglong2 index within a cs row

    for (int kt = 0; kt < DIM; kt += KT) {
        __syncthreads();
        // center tile transposed: cs[kk][c] = cc[cblk*256 + c][kt+kk]
#pragma unroll
        for (int j = 0; j < 8; ++j) {
            int c = tx;                      // 0..255
            float4 v = *reinterpret_cast<const float4*>(
                cc + (size_t)(cblk * CTILE + c) * DIM + kt + j * 4);
            cs[(j * 4 + 0) * CTILE + c] = v.x;
            cs[(j * 4 + 1) * CTILE + c] = v.y;
            cs[(j * 4 + 2) * CTILE + c] = v.z;
            cs[(j * 4 + 3) * CTILE + c] = v.w;
        }
        // x tile duplicated: xs2[kk][r] = (x, x)
        {
            int r = tx & 31;
            int q = tx >> 5;  // 0..7
            float4 v = *reinterpret_cast<const float4*>(
                x + (size_t)(row0 + r) * DIM + kt + q * 4);
            xs2[(q * 4 + 0) * MTILE + r] = make_float2(v.x, v.x);
            xs2[(q * 4 + 1) * MTILE + r] = make_float2(v.y, v.y);
            xs2[(q * 4 + 2) * MTILE + r] = make_float2(v.z, v.z);
            xs2[(q * 4 + 3) * MTILE + r] = make_float2(v.w, v.w);
        }
        __syncthreads();

        // strict sequential ascending-k FMA chain per (row, center) — bit-exact
#pragma unroll 8
        for (int kk = 0; kk < KT; ++kk) {
            const ulonglong2* crow = reinterpret_cast<const ulonglong2*>(cs + kk * CTILE);
            const unsigned long long* xrow =
                reinterpret_cast<const unsigned long long*>(xs2 + kk * MTILE);
            ulonglong2 ca = crow[cq];        // centers cloc..cloc+3
#pragma unroll
            for (int r = 0; r < 8; ++r) {
                unsigned long long xv = xrow[rbase + r];
                acc[r][0] = fma2(xv, ca.x, acc[r][0]);
                acc[r][1] = fma2(xv, ca.y, acc[r][1]);
            }
        }
    }

    // epilogue: dist = sqrt(max((x2 - 2*dot) + c2, 0)), exact ref rounding
    float4 c2v = *reinterpret_cast<const float4*>(g_c2 + cglob);
#pragma unroll
    for (int r = 0; r < 8; ++r) {
        int rl = rbase + r;
        float x2v = x2s[rl];
        float l0, h0, l1, h1;
        unpack2(acc[r][0], l0, h0);
        unpack2(acc[r][1], l1, h1);
        float4 dv;
        dv.x = __fsqrt_rn(fmaxf(__fadd_rn(__fsub_rn(x2v, 2.0f * l0), c2v.x), 0.0f));
        dv.y = __fsqrt_rn(fmaxf(__fadd_rn(__fsub_rn(x2v, 2.0f * h0), c2v.y), 0.0f));
        dv.z = __fsqrt_rn(fmaxf(__fadd_rn(__fsub_rn(x2v, 2.0f * l1), c2v.z), 0.0f));
        dv.w = __fsqrt_rn(fmaxf(__fadd_rn(__fsub_rn(x2v, 2.0f * h1), c2v.w), 0.0f));
        *reinterpret_cast<float4*>(g_scores + (size_t)(row0 + rl) * NC + cglob) = dv;
    }
}

// ========================= Kernel B: top-k select + gather =========================
#define OFF_SC    0
#define OFF_CAND  (MTILE * NC * 4)              // 65536
#define OFF_FIDX  (OFF_CAND + MTILE * CAND_STRIDE * 8)
#define GB_SMEM   (OFF_FIDX + MTILE * TOPK * 4) // 87552

__global__ __launch_bounds__(256, 2)
void topk_kernel(const float* __restrict__ x, float* __restrict__ out) {
    extern __shared__ char smraw[];
    float* score = reinterpret_cast<float*>(smraw + OFF_SC);              // [MTILE][NC]
    unsigned long long* cand =
        reinterpret_cast<unsigned long long*>(smraw + OFF_CAND);          // [MTILE][81]
    int* fidx = reinterpret_cast<int*>(smraw + OFF_FIDX);                 // [MTILE][10]

    const int tx   = threadIdx.x;
    const int row0 = blockIdx.x * MTILE;

    // stage scores global -> smem, coalesced float4
    {
        const float4* src = reinterpret_cast<const float4*>(g_scores + (size_t)row0 * NC);
        float4* dst = reinterpret_cast<float4*>(score);
#pragma unroll
        for (int j = 0; j < 16; ++j) dst[tx + 256 * j] = src[tx + 256 * j];
    }
    __syncthreads();

    // per-row local top-10 on packed keys (dist_bits<<32 | idx)
    {
        const int tsub = tx & 7;
        const int rl = tx >> 3;
        const int cb = tsub * 64;
        const int rot = tx & 63;
        unsigned long long bs[TOPK];
#pragma unroll
        for (int p = 0; p < TOPK; ++p) bs[p] = ~0ull;
        for (int v = 0; v < 64; ++v) {
            int c = cb + ((v + rot) & 63);
            float s = score[rl * NC + c];
            unsigned long long key =
                ((unsigned long long)__float_as_uint(s) << 32) | (unsigned)c;
            if (key < bs[TOPK - 1]) {
                bs[TOPK - 1] = key;
#pragma unroll
                for (int p = TOPK - 1; p > 0; --p) {
                    if (bs[p] < bs[p - 1]) {
                        unsigned long long t = bs[p]; bs[p] = bs[p - 1]; bs[p - 1] = t;
                    }
                }
            }
        }
#pragma unroll
        for (int p = 0; p < TOPK; ++p)
            cand[rl * CAND_STRIDE + tsub * TOPK + p] = bs[p];
    }
    __syncthreads();

    // merge 80 -> 10 per row
    if (tx < MTILE) {
        const int rl = tx;
        unsigned long long bs[TOPK];
#pragma unroll
        for (int p = 0; p < TOPK; ++p) bs[p] = ~0ull;
        for (int v = 0; v < 8 * TOPK; ++v) {
            unsigned long long key = cand[rl * CAND_STRIDE + v];
            if (key < bs[TOPK - 1]) {
                bs[TOPK - 1] = key;
#pragma unroll
                for (int p = TOPK - 1; p > 0; --p) {
                    if (bs[p] < bs[p - 1]) {
                        unsigned long long t = bs[p]; bs[p] = bs[p - 1]; bs[p - 1] = t;
                    }
                }
            }
        }
#pragma unroll
        for (int p = 0; p < TOPK; ++p)
            fidx[rl * TOPK + p] = (int)(unsigned)(bs[p] & 0xffffffffu);
    }
    __syncthreads();

    // gather epilogue: out[row*10+t] = x[idx]  (idx < 512 -> L2-hot)
    {
        const float4* x4 = reinterpret_cast<const float4*>(x);
        float4* out4 = reinterpret_cast<float4*>(out);
#pragma unroll
        for (int it = 0; it < 40; ++it) {
            int i = tx + 256 * it;          // 0 .. 10239
            int orow = i >> 5;              // 0 .. 319
            int e = i & 31;
            int rl = orow / 10;
            int t = orow - rl * 10;
            int idx = fidx[rl * TOPK + t];
            size_t src = (size_t)idx * 32 + e;
            size_t dst = ((size_t)(row0 + rl) * 10 + t) * 32 + e;
            out4[dst] = __ldg(&x4[src]);
        }
    }
}

extern "C" void kernel_launch(void* const* d_in, const int* in_sizes, int n_in,
                              void* d_out, int out_size) {
    const float* x  = (const float*)d_in[0];
    const float* cc = (const float*)d_in[1];
    float* out = (float*)d_out;

    cudaFuncSetAttribute(gemm_kernel,
                         cudaFuncAttributeMaxDynamicSharedMemorySize, GA_SMEM);
    cudaFuncSetAttribute(topk_kernel,
                         cudaFuncAttributeMaxDynamicSharedMemorySize, GB_SMEM);
    c2_kernel<<<NC / 8, 256>>>(cc);
    gemm_kernel<<<(NROWS / MTILE) * 2, 256, GA_SMEM>>>(x, cc);
    topk_kernel<<<NROWS / MTILE, 256, GB_SMEM>>>(x, out);
}

// round 8
// speedup vs baseline: 1.1500x; 1.1500x over previous
#include <cuda_runtime.h>

#define NROWS 32768
#define DIM   128
#define NC    512
#define TOPK  10
#define MTILE 32
#define KT    32
#define NTHR  512
#define CAND_STRIDE 81                 // padded candidate row stride (u64 keys)

// smem layout offsets (bytes)
#define OFF_CS    0                     // cs [KT][NC] f32 = 64KB ; score overlays
#define OFF_XS2   65536                 // xs2 [KT][MTILE] float2 dup = 8KB
#define OFF_X2S   (OFF_XS2 + 8192)      // x2s [MTILE] f32 = 128B
#define OFF_CAND  (OFF_X2S + 128)       // cand [MTILE][81] u64 = 20736B
#define OFF_FIDX  (OFF_CAND + 20736)    // fidx [MTILE][10] i32 = 1280B
#define SMEM_TOTAL (OFF_FIDX + 1280)    // 95872 -> 2 CTAs/SM

__device__ float g_c2[NC];

// XLA GPU row-reduction for sum(v*v), 128-wide f32 row:
// single pass, 16-byte vectorized: lane t owns contiguous quad v[4t..4t+3],
// left-fold into scalar partial, then shfl_down tree offsets 16,8,4,2,1.
// (empirically bit-exact vs the reference — DO NOT CHANGE)
__device__ __forceinline__ float xla_row_sumsq(const float* __restrict__ row, int lane) {
    float4 v = *reinterpret_cast<const float4*>(row + 4 * lane);
    float p = __fmul_rn(v.x, v.x);
    p = __fadd_rn(p, __fmul_rn(v.y, v.y));
    p = __fadd_rn(p, __fmul_rn(v.z, v.z));
    p = __fadd_rn(p, __fmul_rn(v.w, v.w));
#pragma unroll
    for (int off = 16; off > 0; off >>= 1)
        p = __fadd_rn(p, __shfl_down_sync(0xffffffffu, p, off));
    return __shfl_sync(0xffffffffu, p, 0);
}

__global__ void c2_kernel(const float* __restrict__ cc) {
    int warp = threadIdx.x >> 5;
    int lane = threadIdx.x & 31;
    int c = blockIdx.x * 8 + warp;
    float s = xla_row_sumsq(cc + (size_t)c * DIM, lane);
    if (lane == 0) g_c2[c] = s;
}

__device__ __forceinline__ unsigned long long fma2(unsigned long long a,
                                                   unsigned long long b,
                                                   unsigned long long c) {
    unsigned long long d;
    asm("fma.rn.f32x2 %0, %1, %2, %3;" : "=l"(d) : "l"(a), "l"(b), "l"(c));
    return d;
}
__device__ __forceinline__ void unpack2(unsigned long long v, float& lo, float& hi) {
    asm("mov.b64 {%0, %1}, %2;" : "=f"(lo), "=f"(hi) : "l"(v));
}

__global__ __launch_bounds__(NTHR, 2)
void kmeans_topk_kernel(const float* __restrict__ x,
                        const float* __restrict__ cc,
                        float* __restrict__ out) {
    extern __shared__ char smraw[];
    float*  cs    = reinterpret_cast<float*>(smraw + OFF_CS);     // [KT][NC]
    float2* xs2   = reinterpret_cast<float2*>(smraw + OFF_XS2);   // [KT][MTILE]
    float*  x2s   = reinterpret_cast<float*>(smraw + OFF_X2S);    // [MTILE]
    unsigned long long* cand =
        reinterpret_cast<unsigned long long*>(smraw + OFF_CAND);  // [MTILE][81]
    int*    fidx  = reinterpret_cast<int*>(smraw + OFF_FIDX);     // [MTILE][10]
    float*  score = cs;                                           // overlay [MTILE][NC]

    const int tx   = threadIdx.x;
    const int row0 = blockIdx.x * MTILE;
    const int lane = tx & 31;
    const int warp = tx >> 5;          // 0..15
    const int rg   = warp >> 2;        // 0..3 row groups (8 rows each)
    const int cg   = warp & 3;         // 0..3 center quarters (128 each)
    const int rbase = rg * 8;
    const int cL   = cg * 128 + lane * 4;  // this thread's 4 centers

    // x2[row] exact XLA order; warp w does rows w and w+16
#pragma unroll
    for (int j = 0; j < 2; ++j) {
        int rl = warp + 16 * j;
        float s = xla_row_sumsq(x + (size_t)(row0 + rl) * DIM, lane);
        if (lane == 0) x2s[rl] = s;
    }

    // acc[r][j]: j=0 -> centers (cL,cL+1); j=1 -> (cL+2,cL+3)
    unsigned long long acc[8][2];
#pragma unroll
    for (int r = 0; r < 8; ++r) { acc[r][0] = 0ull; acc[r][1] = 0ull; }

    const int cq = cL >> 2;          // ulonglong2 index within a cs row

    for (int kt = 0; kt < DIM; kt += KT) {
        __syncthreads();
        // ---- center chunk transposed: cs[kk][c] = cc[c][kt+kk] ----
#pragma unroll
        for (int j = 0; j < 8; ++j) {
            int i = tx + NTHR * j;
            int c = i & (NC - 1);
            int q = i >> 9;  // 0..7
            float4 v = *reinterpret_cast<const float4*>(cc + (size_t)c * DIM + kt + q * 4);
            cs[(q * 4 + 0) * NC + c] = v.x;
            cs[(q * 4 + 1) * NC + c] = v.y;
            cs[(q * 4 + 2) * NC + c] = v.z;
            cs[(q * 4 + 3) * NC + c] = v.w;
        }
        // ---- x chunk duplicated: xs2[kk][r] = (x,x) ----
        if (tx < 256) {
            int r = tx & 31;
            int q = tx >> 5;  // 0..7
            float4 v = *reinterpret_cast<const float4*>(x + (size_t)(row0 + r) * DIM + kt + q * 4);
            xs2[(q * 4 + 0) * MTILE + r] = make_float2(v.x, v.x);
            xs2[(q * 4 + 1) * MTILE + r] = make_float2(v.y, v.y);
            xs2[(q * 4 + 2) * MTILE + r] = make_float2(v.z, v.z);
            xs2[(q * 4 + 3) * MTILE + r] = make_float2(v.w, v.w);
        }
        __syncthreads();

        // strict sequential ascending-k FMA chain per (row, center) — bit-exact
#pragma unroll 8
        for (int kk = 0; kk < KT; ++kk) {
            const ulonglong2* crow = reinterpret_cast<const ulonglong2*>(cs + kk * NC);
            const ulonglong2* xrow = reinterpret_cast<const ulonglong2*>(xs2 + kk * MTILE);
            ulonglong2 ca  = crow[cq];            // centers cL..cL+3 (1 LDS.128)
            ulonglong2 x01 = xrow[(rbase >> 1) + 0];  // rows rbase..+7, broadcast
            ulonglong2 x23 = xrow[(rbase >> 1) + 1];
            ulonglong2 x45 = xrow[(rbase >> 1) + 2];
            ulonglong2 x67 = xrow[(rbase >> 1) + 3];
            unsigned long long xv[8] = {x01.x, x01.y, x23.x, x23.y,
                                        x45.x, x45.y, x67.x, x67.y};
#pragma unroll
            for (int r = 0; r < 8; ++r) {
                acc[r][0] = fma2(xv[r], ca.x, acc[r][0]);
                acc[r][1] = fma2(xv[r], ca.y, acc[r][1]);
            }
        }
    }
    __syncthreads();

    // ---- scores: dist = sqrt(max((x2 - 2*dot) + c2, 0)), exact ref rounding ----
    {
        float4 c2v = *reinterpret_cast<const float4*>(g_c2 + cL);
#pragma unroll
        for (int r = 0; r < 8; ++r) {
            int rl = rbase + r;
            float x2v = x2s[rl];
            float l0, h0, l1, h1;
            unpack2(acc[r][0], l0, h0);
            unpack2(acc[r][1], l1, h1);
            float4 dv;
            dv.x = __fsqrt_rn(fmaxf(__fadd_rn(__fsub_rn(x2v, 2.0f * l0), c2v.x), 0.0f));
            dv.y = __fsqrt_rn(fmaxf(__fadd_rn(__fsub_rn(x2v, 2.0f * h0), c2v.y), 0.0f));
            dv.z = __fsqrt_rn(fmaxf(__fadd_rn(__fsub_rn(x2v, 2.0f * l1), c2v.z), 0.0f));
            dv.w = __fsqrt_rn(fmaxf(__fadd_rn(__fsub_rn(x2v, 2.0f * h1), c2v.w), 0.0f));
            *reinterpret_cast<float4*>(&score[rl * NC + cL]) = dv;
        }
    }
    __syncthreads();

    // ---- per-row local top-10 on packed keys (dist_bits<<32 | idx) ----
    if (tx < 256) {
        const int tsub = tx & 7;
        const int rl = tx >> 3;
        const int cb = tsub * 64;
        const int rot = tx & 63;  // bank-spreading rotation (order-safe: keys)
        unsigned long long bs[TOPK];
#pragma unroll
        for (int p = 0; p < TOPK; ++p) bs[p] = ~0ull;
        for (int v = 0; v < 64; ++v) {
            int c = cb + ((v + rot) & 63);
            float s = score[rl * NC + c];
            unsigned long long key =
                ((unsigned long long)__float_as_uint(s) << 32) | (unsigned)c;
            if (key < bs[TOPK - 1]) {
                bs[TOPK - 1] = key;
#pragma unroll
                for (int p = TOPK - 1; p > 0; --p) {
                    if (bs[p] < bs[p - 1]) {
                        unsigned long long t = bs[p]; bs[p] = bs[p - 1]; bs[p - 1] = t;
                    }
                }
            }
        }
#pragma unroll
        for (int p = 0; p < TOPK; ++p)
            cand[rl * CAND_STRIDE + tsub * TOPK + p] = bs[p];
    }
    __syncthreads();

    // ---- merge 80 -> 10 per row ----
    if (tx < MTILE) {
        const int rl = tx;
        unsigned long long bs[TOPK];
#pragma unroll
        for (int p = 0; p < TOPK; ++p) bs[p] = ~0ull;
        for (int v = 0; v < 8 * TOPK; ++v) {
            unsigned long long key = cand[rl * CAND_STRIDE + v];
            if (key < bs[TOPK - 1]) {
                bs[TOPK - 1] = key;
#pragma unroll
                for (int p = TOPK - 1; p > 0; --p) {
                    if (bs[p] < bs[p - 1]) {
                        unsigned long long t = bs[p]; bs[p] = bs[p - 1]; bs[p - 1] = t;
                    }
                }
            }
        }
#pragma unroll
        for (int p = 0; p < TOPK; ++p)
            fidx[rl * TOPK + p] = (int)(unsigned)(bs[p] & 0xffffffffu);
    }
    __syncthreads();

    // ---- gather epilogue: out[row*10+t] = x[idx]  (idx < 512 -> L2-hot) ----
    {
        const float4* x4 = reinterpret_cast<const float4*>(x);
        float4* out4 = reinterpret_cast<float4*>(out);
#pragma unroll
        for (int it = 0; it < 20; ++it) {
            int i = tx + NTHR * it;         // 0 .. 10239
            int orow = i >> 5;              // 0 .. 319
            int e = i & 31;
            int rl = orow / 10;
            int t = orow - rl * 10;
            int idx = fidx[rl * TOPK + t];
            size_t src = (size_t)idx * 32 + e;
            size_t dst = ((size_t)(row0 + rl) * 10 + t) * 32 + e;
            out4[dst] = __ldg(&x4[src]);
        }
    }
}

extern "C" void kernel_launch(void* const* d_in, const int* in_sizes, int n_in,
                              void* d_out, int out_size) {
    const float* x  = (const float*)d_in[0];
    const float* cc = (const float*)d_in[1];
    float* out = (float*)d_out;

    cudaFuncSetAttribute(kmeans_topk_kernel,
                         cudaFuncAttributeMaxDynamicSharedMemorySize, SMEM_TOTAL);
    c2_kernel<<<NC / 8, 256>>>(cc);
    kmeans_topk_kernel<<<NROWS / MTILE, NTHR, SMEM_TOTAL>>>(x, cc, out);
}

// round 9
// speedup vs baseline: 1.2458x; 1.0833x over previous
#include <cuda_runtime.h>

#define NROWS 32768
#define DIM   128
#define NC    512
#define TOPK  10
#define MTILE 32
#define KT    32
#define NTHR  256
#define CAND_STRIDE 81                 // padded candidate row stride (u64 keys)

// smem layout offsets (bytes)
#define OFF_CS    0                     // cs [KT][NC] f32 = 64KB ; score overlays
#define OFF_XS    65536                 // xs [KT][MTILE] f32 (NOT duplicated) = 4KB
#define OFF_X2S   (OFF_XS + 4096)       // x2s [MTILE] f32
#define OFF_CAND  (OFF_X2S + 128)       // cand [MTILE][81] u64
#define OFF_FIDX  (OFF_CAND + 20736)    // fidx [MTILE][10] i32
#define SMEM_TOTAL (OFF_FIDX + 1280)    // 91776 -> 2 CTAs/SM

__device__ float g_c2[NC];

// XLA GPU row-reduction for sum(v*v), 128-wide f32 row:
// single pass, 16-byte vectorized: lane t owns contiguous quad v[4t..4t+3],
// left-fold into scalar partial, then shfl_down tree offsets 16,8,4,2,1.
// (empirically bit-exact vs the reference — DO NOT CHANGE)
__device__ __forceinline__ float xla_row_sumsq(const float* __restrict__ row, int lane) {
    float4 v = *reinterpret_cast<const float4*>(row + 4 * lane);
    float p = __fmul_rn(v.x, v.x);
    p = __fadd_rn(p, __fmul_rn(v.y, v.y));
    p = __fadd_rn(p, __fmul_rn(v.z, v.z));
    p = __fadd_rn(p, __fmul_rn(v.w, v.w));
#pragma unroll
    for (int off = 16; off > 0; off >>= 1)
        p = __fadd_rn(p, __shfl_down_sync(0xffffffffu, p, off));
    return __shfl_sync(0xffffffffu, p, 0);
}

__global__ void c2_kernel(const float* __restrict__ cc) {
    int warp = threadIdx.x >> 5;
    int lane = threadIdx.x & 31;
    int c = blockIdx.x * 8 + warp;
    float s = xla_row_sumsq(cc + (size_t)c * DIM, lane);
    if (lane == 0) g_c2[c] = s;
}

__device__ __forceinline__ unsigned long long fma2(unsigned long long a,
                                                   unsigned long long b,
                                                   unsigned long long c) {
    unsigned long long d;
    asm("fma.rn.f32x2 %0, %1, %2, %3;" : "=l"(d) : "l"(a), "l"(b), "l"(c));
    return d;
}
__device__ __forceinline__ unsigned long long pack2(float f) {
    unsigned long long d;
    asm("mov.b64 %0, {%1, %1};" : "=l"(d) : "f"(f));
    return d;
}
__device__ __forceinline__ void unpack2(unsigned long long v, float& lo, float& hi) {
    asm("mov.b64 {%0, %1}, %2;" : "=f"(lo), "=f"(hi) : "l"(v));
}

__global__ __launch_bounds__(NTHR, 2)
void kmeans_topk_kernel(const float* __restrict__ x,
                        const float* __restrict__ cc,
                        float* __restrict__ out) {
    extern __shared__ char smraw[];
    float*  cs    = reinterpret_cast<float*>(smraw + OFF_CS);     // [KT][NC]
    float*  xs    = reinterpret_cast<float*>(smraw + OFF_XS);     // [KT][MTILE] scalar
    float*  x2s   = reinterpret_cast<float*>(smraw + OFF_X2S);    // [MTILE]
    unsigned long long* cand =
        reinterpret_cast<unsigned long long*>(smraw + OFF_CAND);  // [MTILE][81]
    int*    fidx  = reinterpret_cast<int*>(smraw + OFF_FIDX);     // [MTILE][10]
    float*  score = cs;                                           // overlay [MTILE][NC]

    const int tx   = threadIdx.x;
    const int row0 = blockIdx.x * MTILE;
    const int lane = tx & 31;
    const int warp = tx >> 5;          // 0..7
    const int rg   = warp >> 1;        // 0..3 row groups (8 rows each)
    const int cg   = warp & 1;         // 0..1 center halves (256 each)
    const int rbase = rg * 8;
    const int cL   = cg * 256 + lane * 4;  // centers cL..cL+3 and cL+128..cL+131

    // x2[row] exact XLA order; warp w does rows w, w+8, w+16, w+24
#pragma unroll
    for (int j = 0; j < 4; ++j) {
        int rl = warp + 8 * j;
        float s = xla_row_sumsq(x + (size_t)(row0 + rl) * DIM, lane);
        if (lane == 0) x2s[rl] = s;
    }

    // acc[r][j]: j=0,1 -> centers (cL..cL+3); j=2,3 -> (cL+128..cL+131)
    unsigned long long acc[8][4];
#pragma unroll
    for (int r = 0; r < 8; ++r)
#pragma unroll
        for (int j = 0; j < 4; ++j) acc[r][j] = 0ull;

    const int cq = cL >> 2;   // ulonglong2 index within a cs row

    for (int kt = 0; kt < DIM; kt += KT) {
        __syncthreads();
        // ---- center chunk transposed: cs[kk][c] = cc[c][kt+kk] ----
#pragma unroll
        for (int j = 0; j < 16; ++j) {
            int i = tx + NTHR * j;
            int c = i & (NC - 1);
            int q = i >> 9;  // 0..7
            float4 v = *reinterpret_cast<const float4*>(cc + (size_t)c * DIM + kt + q * 4);
            cs[(q * 4 + 0) * NC + c] = v.x;
            cs[(q * 4 + 1) * NC + c] = v.y;
            cs[(q * 4 + 2) * NC + c] = v.z;
            cs[(q * 4 + 3) * NC + c] = v.w;
        }
        // ---- x chunk scalar (no duplication): xs[kk][r] = x ----
        {
            int r = tx & 31;
            int q = tx >> 5;  // 0..7
            float4 v = *reinterpret_cast<const float4*>(x + (size_t)(row0 + r) * DIM + kt + q * 4);
            xs[(q * 4 + 0) * MTILE + r] = v.x;
            xs[(q * 4 + 1) * MTILE + r] = v.y;
            xs[(q * 4 + 2) * MTILE + r] = v.z;
            xs[(q * 4 + 3) * MTILE + r] = v.w;
        }
        __syncthreads();

        // strict sequential ascending-k FMA chain per (row, center) — bit-exact
#pragma unroll 4
        for (int kk = 0; kk < KT; ++kk) {
            const ulonglong2* crow = reinterpret_cast<const ulonglong2*>(cs + kk * NC);
            const float* xrow = xs + kk * MTILE + rbase;
            ulonglong2 ca = crow[cq];        // centers cL..cL+3   (1 LDS.128)
            ulonglong2 cb = crow[cq + 32];   // centers cL+128..+131
#pragma unroll
            for (int r = 0; r < 8; ++r) {
                unsigned long long xv = pack2(xrow[r]);  // 4B broadcast LDS + reg pack
                acc[r][0] = fma2(xv, ca.x, acc[r][0]);
                acc[r][1] = fma2(xv, ca.y, acc[r][1]);
                acc[r][2] = fma2(xv, cb.x, acc[r][2]);
                acc[r][3] = fma2(xv, cb.y, acc[r][3]);
            }
        }
    }
    __syncthreads();

    // ---- scores: dist = sqrt(max((x2 - 2*dot) + c2, 0)), exact ref rounding ----
    {
        float4 c2a = *reinterpret_cast<const float4*>(g_c2 + cL);
        float4 c2b = *reinterpret_cast<const float4*>(g_c2 + cL + 128);
#pragma unroll
        for (int r = 0; r < 8; ++r) {
            int rl = rbase + r;
            float x2v = x2s[rl];
            float l0, h0, l1, h1, l2, h2, l3, h3;
            unpack2(acc[r][0], l0, h0);
            unpack2(acc[r][1], l1, h1);
            unpack2(acc[r][2], l2, h2);
            unpack2(acc[r][3], l3, h3);
            float4 da, db;
            da.x = __fsqrt_rn(fmaxf(__fadd_rn(__fsub_rn(x2v, 2.0f * l0), c2a.x), 0.0f));
            da.y = __fsqrt_rn(fmaxf(__fadd_rn(__fsub_rn(x2v, 2.0f * h0), c2a.y), 0.0f));
            da.z = __fsqrt_rn(fmaxf(__fadd_rn(__fsub_rn(x2v, 2.0f * l1), c2a.z), 0.0f));
            da.w = __fsqrt_rn(fmaxf(__fadd_rn(__fsub_rn(x2v, 2.0f * h1), c2a.w), 0.0f));
            db.x = __fsqrt_rn(fmaxf(__fadd_rn(__fsub_rn(x2v, 2.0f * l2), c2b.x), 0.0f));
            db.y = __fsqrt_rn(fmaxf(__fadd_rn(__fsub_rn(x2v, 2.0f * h2), c2b.y), 0.0f));
            db.z = __fsqrt_rn(fmaxf(__fadd_rn(__fsub_rn(x2v, 2.0f * l3), c2b.z), 0.0f));
            db.w = __fsqrt_rn(fmaxf(__fadd_rn(__fsub_rn(x2v, 2.0f * h3), c2b.w), 0.0f));
            *reinterpret_cast<float4*>(&score[rl * NC + cL]) = da;
            *reinterpret_cast<float4*>(&score[rl * NC + cL + 128]) = db;
        }
    }
    __syncthreads();

    // ---- per-row local top-10 on packed keys (dist_bits<<32 | idx) ----
    {
        const int tsub = tx & 7;
        const int rl = tx >> 3;
        const int cb = tsub * 64;
        const int rot = tx & 63;  // bank-spreading rotation (order-safe: keys)
        unsigned long long bs[TOPK];
#pragma unroll
        for (int p = 0; p < TOPK; ++p) bs[p] = ~0ull;
        for (int v = 0; v < 64; ++v) {
            int c = cb + ((v + rot) & 63);
            float s = score[rl * NC + c];
            unsigned long long key =
                ((unsigned long long)__float_as_uint(s) << 32) | (unsigned)c;
            if (key < bs[TOPK - 1]) {
                bs[TOPK - 1] = key;
#pragma unroll
                for (int p = TOPK - 1; p > 0; --p) {
                    if (bs[p] < bs[p - 1]) {
                        unsigned long long t = bs[p]; bs[p] = bs[p - 1]; bs[p - 1] = t;
                    }
                }
            }
        }
#pragma unroll
        for (int p = 0; p < TOPK; ++p)
            cand[rl * CAND_STRIDE + tsub * TOPK + p] = bs[p];
    }
    __syncthreads();

    // ---- merge 80 -> 10 per row ----
    if (tx < MTILE) {
        const int rl = tx;
        unsigned long long bs[TOPK];
#pragma unroll
        for (int p = 0; p < TOPK; ++p) bs[p] = ~0ull;
        for (int v = 0; v < 8 * TOPK; ++v) {
            unsigned long long key = cand[rl * CAND_STRIDE + v];
            if (key < bs[TOPK - 1]) {
                bs[TOPK - 1] = key;
#pragma unroll
                for (int p = TOPK - 1; p > 0; --p) {
                    if (bs[p] < bs[p - 1]) {
                        unsigned long long t = bs[p]; bs[p] = bs[p - 1]; bs[p - 1] = t;
                    }
                }
            }
        }
#pragma unroll
        for (int p = 0; p < TOPK; ++p)
            fidx[rl * TOPK + p] = (int)(unsigned)(bs[p] & 0xffffffffu);
    }
    __syncthreads();

    // ---- gather epilogue: out[row*10+t] = x[idx]  (idx < 512 -> L2-hot) ----
    {
        const float4* x4 = reinterpret_cast<const float4*>(x);
        float4* out4 = reinterpret_cast<float4*>(out);
#pragma unroll
        for (int it = 0; it < 40; ++it) {
            int i = tx + NTHR * it;         // 0 .. 10239
            int orow = i >> 5;              // 0 .. 319
            int e = i & 31;
            int rl = orow / 10;
            int t = orow - rl * 10;
            int idx = fidx[rl * TOPK + t];
            size_t src = (size_t)idx * 32 + e;
            size_t dst = ((size_t)(row0 + rl) * 10 + t) * 32 + e;
            out4[dst] = __ldg(&x4[src]);
        }
    }
}

extern "C" void kernel_launch(void* const* d_in, const int* in_sizes, int n_in,
                              void* d_out, int out_size) {
    const float* x  = (const float*)d_in[0];
    const float* cc = (const float*)d_in[1];
    float* out = (float*)d_out;

    cudaFuncSetAttribute(kmeans_topk_kernel,
                         cudaFuncAttributeMaxDynamicSharedMemorySize, SMEM_TOTAL);
    c2_kernel<<<NC / 8, 256>>>(cc);
    kmeans_topk_kernel<<<NROWS / MTILE, NTHR, SMEM_TOTAL>>>(x, cc, out);
}